// round 4
// baseline (speedup 1.0000x reference)
#include <cuda_runtime.h>
#include <math.h>
#include <stdint.h>

// Problem shape (fixed by the reference setup_inputs)
#define BB 32
#define PP 8732
#define CC 81
#define NPRI (BB * PP)             // 279424 rows
#define TROWS 32                   // rows per tile
#define NTILES (NPRI / TROWS)      // 8732 (exact)
#define TILE_FLOATS (TROWS * CC)   // 2592
#define TILE_F4 (TILE_FLOATS / 4)  // 648
#define LAB_F4 (TROWS / 4)         // 8 (labels staged as int4)
#define STAGE_F4 (TILE_F4 + LAB_F4)// 656 float4 = 10496 B
#define STAGES 3
#define TPB 256
#define G 1024                     // conf-pipeline blocks (also total grid)

// Scratch (static __device__ — no allocation allowed)
__device__ float g_ce[NPRI];      // per-prior CE
__device__ float g_bg[NPRI];      // per-prior bg loss, -inf on positives
__device__ float g_cepart[G];     // per-block partial CE sum
__device__ float g_sl1[BB];       // per-batch smooth-L1 sum over positives
__device__ int   g_npos[BB];      // per-batch positive count
__device__ float g_cesum[BB];     // per-batch masked CE (slow path)
__device__ int   g_ctr;           // k1 finisher counter (zero-init, reset each call)
__device__ int   g_ctr2;          // k2 finisher counter
__device__ int   g_fastdone;      // 1 => k1 already wrote out[]

__device__ __forceinline__ void cp16(uint32_t dst_smem, const void* src) {
    asm volatile("cp.async.cg.shared.global [%0], [%1], 16;" :: "r"(dst_smem), "l"(src));
}
__device__ __forceinline__ void cp_commit() {
    asm volatile("cp.async.commit_group;");
}
template <int N> __device__ __forceinline__ void cp_wait() {
    asm volatile("cp.async.wait_group %0;" :: "n"(N));
}

// ---------------------------------------------------------------------------
// k1: single fused kernel, G=1024 blocks.
//  All blocks: stream a contiguous chunk of conf tiles through a 3-stage
//  cp.async pipeline (loads overlap compute). Blocks 0..31 additionally do
//  the loc path (per-batch npos + smooth-L1) first.
//  Last block finalizes: if every batch has 3*num_pos >= P (mask == all),
//  writes out[] directly and k2 becomes a no-op.
// ---------------------------------------------------------------------------
__global__ void __launch_bounds__(TPB) k1(const float* __restrict__ conf,
                                          const float* __restrict__ pred,
                                          const float* __restrict__ gt,
                                          const int* __restrict__ labels,
                                          float* __restrict__ out) {
    __shared__ float4 stg[STAGES][STAGE_F4];   // 31488 B
    __shared__ float  sred[TPB];
    __shared__ int    sint[TPB];
    __shared__ int    s_last;
    const int bx   = blockIdx.x;
    const int tid  = threadIdx.x;
    const int lane = tid & 31;
    const int wid  = tid >> 5;
    const unsigned FULL = 0xffffffffu;

    // ================= loc path (blocks 0..31, one per batch) =================
    if (bx < BB) {
        const int base = bx * PP;
        int   np  = 0;
        float sl1 = 0.f;
        for (int p = tid; p < PP; p += TPB) {
            const int lab = labels[base + p];
            if (lab > 0) {
                np++;
                const float4 pv = *reinterpret_cast<const float4*>(pred + (size_t)(base + p) * 4);
                const float4 gv = *reinterpret_cast<const float4*>(gt   + (size_t)(base + p) * 4);
                float d, ad;
                d = pv.x - gv.x; ad = fabsf(d); sl1 += (ad < 1.f) ? 0.5f * d * d : ad - 0.5f;
                d = pv.y - gv.y; ad = fabsf(d); sl1 += (ad < 1.f) ? 0.5f * d * d : ad - 0.5f;
                d = pv.z - gv.z; ad = fabsf(d); sl1 += (ad < 1.f) ? 0.5f * d * d : ad - 0.5f;
                d = pv.w - gv.w; ad = fabsf(d); sl1 += (ad < 1.f) ? 0.5f * d * d : ad - 0.5f;
            }
        }
        sred[tid] = sl1;
        sint[tid] = np;
        __syncthreads();
        for (int st = TPB / 2; st > 0; st >>= 1) {
            if (tid < st) { sred[tid] += sred[tid + st]; sint[tid] += sint[tid + st]; }
            __syncthreads();
        }
        if (tid == 0) { g_sl1[bx] = sred[0]; g_npos[bx] = sint[0]; }
        __syncthreads();
    }

    // ================= conf pipeline =================
    const int start = (int)(((long long)bx * NTILES) / G);
    const int end   = (int)(((long long)(bx + 1) * NTILES) / G);

    const float4* conf4 = reinterpret_cast<const float4*>(conf);
    const int4*   lab4  = reinterpret_cast<const int4*>(labels);

    // issue one stage's worth of cp.async for tile t into stage s
    auto issue = [&](int t, int s) {
        uint32_t sbase = (uint32_t)__cvta_generic_to_shared(&stg[s][0]);
        for (int i = tid; i < STAGE_F4; i += TPB) {
            const void* src = (i < TILE_F4)
                ? (const void*)(conf4 + (size_t)t * TILE_F4 + i)
                : (const void*)(lab4 + (size_t)t * LAB_F4 + (i - TILE_F4));
            cp16(sbase + (uint32_t)i * 16u, src);
        }
    };

    float ce_acc = 0.f;
    const int row = (wid << 2) + (lane >> 3);  // 4 rows per warp
    const int sub = lane & 7;                  // 8 workers per row

    // prologue
    if (start < end)     issue(start, 0);
    cp_commit();
    if (start + 1 < end) issue(start + 1, 1);
    cp_commit();

    for (int t = start; t < end; t++) {
        const int s = (t - start) % STAGES;
        cp_wait<STAGES - 2>();   // tile t's data (this thread's groups) done
        __syncthreads();         // make it visible block-wide

        const float* sp   = reinterpret_cast<const float*>(&stg[s][0]);
        const int*   slab = reinterpret_cast<const int*>(sp + TILE_FLOATS);
        const float* rp   = sp + row * CC;

        float a0 = 0.f, a1 = 0.f;
        #pragma unroll
        for (int k = 0; k < 10; k += 2) {
            a0 += __expf(rp[sub + 8 * k]);
            a1 += __expf(rp[sub + 8 * (k + 1)]);
        }
        float a = a0 + a1;
        const int lab = slab[row];
        if (sub == 0) a += __expf(rp[80]);
        a += __shfl_xor_sync(FULL, a, 1);
        a += __shfl_xor_sync(FULL, a, 2);
        a += __shfl_xor_sync(FULL, a, 4);
        if (sub == 0) {
            const float lse  = __logf(a);
            const float pick = rp[lab];
            const float x0   = rp[0];
            const float ce   = lse - pick;
            const int   rg   = t * TROWS + row;
            g_ce[rg] = ce;
            g_bg[rg] = (lab > 0) ? -INFINITY : (lse - x0);
            ce_acc += ce;
        }
        __syncthreads();         // everyone done reading before stage reuse

        const int tn = t + STAGES - 1;
        if (tn < end) issue(tn, (tn - start) % STAGES);
        cp_commit();
    }
    cp_wait<0>();                // drain before exit

    // per-block CE partial (static assignment -> deterministic)
    sred[tid] = ce_acc;
    __syncthreads();
    for (int st = TPB / 2; st > 0; st >>= 1) {
        if (tid < st) sred[tid] += sred[tid + st];
        __syncthreads();
    }
    if (tid == 0) g_cepart[bx] = sred[0];

    // ================= finisher (last block of the grid) =================
    if (tid == 0) {
        __threadfence();
        s_last = (atomicAdd(&g_ctr, 1) == G - 1);
    }
    __syncthreads();
    if (!s_last) return;

    // all-fast check: every batch with 3*num_pos >= P selects every prior
    sint[tid] = (tid < BB) ? (int)((long long)g_npos[tid] * 3 < (long long)PP) : 0;
    __syncthreads();
    for (int st = TPB / 2; st > 0; st >>= 1) {
        if (tid < st) sint[tid] += sint[tid + st];
        __syncthreads();
    }
    const int allfast = (sint[0] == 0);
    __syncthreads();

    if (allfast) {
        float cs = 0.f;
        for (int i = tid; i < G; i += TPB) cs += g_cepart[i];   // fixed order
        sred[tid] = cs;
        __syncthreads();
        for (int st = TPB / 2; st > 0; st >>= 1) {
            if (tid < st) sred[tid] += sred[tid + st];
            __syncthreads();
        }
        if (tid < 32) {  // BB == 32
            float sl = g_sl1[tid];
            int   np = g_npos[tid];
            #pragma unroll
            for (int o = 16; o > 0; o >>= 1) {
                sl += __shfl_xor_sync(FULL, sl, o);
                np += __shfl_xor_sync(FULL, np, o);
            }
            if (tid == 0) {
                const float inv = 1.f / (float)np;
                out[0] = sl * inv;
                out[1] = sred[0] * inv;
                g_fastdone = 1;
                g_ctr = 0;  // reset for next replay
            }
        }
    } else {
        if (tid == 0) { g_fastdone = 0; g_ctr = 0; }
    }
}

// ---------------------------------------------------------------------------
// k2: general path only (no-op when k1 already finalized).
// Per-batch: if num_neg >= P, sum that batch's CE directly; else exact
// hard-negative rank mining (stable-argsort tiebreak) over bg in smem.
// Last block combines and writes out[].
// ---------------------------------------------------------------------------
__global__ void __launch_bounds__(TPB) k2(float* __restrict__ out) {
    if (g_fastdone) return;

    __shared__ float sbg[PP];     // 34928 B
    __shared__ float sred[TPB];
    __shared__ int   s_last;
    const int b   = blockIdx.x;
    const int tid = threadIdx.x;
    const unsigned FULL = 0xffffffffu;
    const int np = g_npos[b];
    const long long num_neg = (long long)np * 3;
    const float* ce = g_ce + b * PP;

    float acc = 0.f;
    if (num_neg >= PP) {
        for (int p = tid; p < PP; p += TPB) acc += ce[p];
    } else {
        const float* bg = g_bg + b * PP;
        for (int p = tid; p < PP; p += TPB) sbg[p] = bg[p];
        __syncthreads();
        for (int p = tid; p < PP; p += TPB) {
            const float v = sbg[p];
            bool sel;
            if (v == -INFINITY) {
                sel = true;       // positive: always selected
            } else {
                int rank = 0;
                for (int j = 0; j < PP; j++) {
                    const float w = sbg[j];
                    rank += (w > v) || (w == v && j < p);
                }
                sel = (rank < num_neg);
            }
            if (sel) acc += ce[p];
        }
    }
    sred[tid] = acc;
    __syncthreads();
    for (int st = TPB / 2; st > 0; st >>= 1) {
        if (tid < st) sred[tid] += sred[tid + st];
        __syncthreads();
    }
    if (tid == 0) g_cesum[b] = sred[0];

    if (tid == 0) {
        __threadfence();
        s_last = (atomicAdd(&g_ctr2, 1) == BB - 1);
    }
    __syncthreads();
    if (!s_last) return;

    if (tid < 32) {  // BB == 32
        float cs = g_cesum[tid];
        float sl = g_sl1[tid];
        int   tn = g_npos[tid];
        #pragma unroll
        for (int o = 16; o > 0; o >>= 1) {
            cs += __shfl_xor_sync(FULL, cs, o);
            sl += __shfl_xor_sync(FULL, sl, o);
            tn += __shfl_xor_sync(FULL, tn, o);
        }
        if (tid == 0) {
            const float inv = 1.f / (float)tn;
            out[0] = sl * inv;
            out[1] = cs * inv;
            g_ctr2 = 0;  // reset for next replay
        }
    }
}

// ---------------------------------------------------------------------------
extern "C" void kernel_launch(void* const* d_in, const int* in_sizes, int n_in,
                              void* d_out, int out_size) {
    const float* conf   = (const float*)d_in[0];   // (32, 8732, 81) f32
    const float* pred   = (const float*)d_in[1];   // (32, 8732, 4)  f32
    const int*   labels = (const int*)d_in[2];     // (32, 8732)     i32
    const float* gt     = (const float*)d_in[3];   // (32, 8732, 4)  f32
    float* out = (float*)d_out;                    // 2 floats

    k1<<<G, TPB>>>(conf, pred, gt, labels, out);
    k2<<<BB, TPB>>>(out);
}

// round 6
// speedup vs baseline: 1.3911x; 1.3911x over previous
#include <cuda_runtime.h>
#include <math.h>
#include <stdint.h>

// Problem shape (fixed by the reference setup_inputs)
#define BB 32
#define PP 8732
#define CC 81
#define NPRI (BB * PP)             // 279424 rows
#define TROWS 32                   // rows per tile
#define NTILES (NPRI / TROWS)      // 8732 (exact)
#define TILE_FLOATS (TROWS * CC)   // 2592
#define TILE_F4 (TILE_FLOATS / 4)  // 648
#define LAB_F4 (TROWS / 4)         // 8 (labels staged as int4)
#define STAGE_F4 (TILE_F4 + LAB_F4)// 656 float4 = 10496 B
#define STAGES 4                   // 41984 B of stages
#define LOOKAHEAD 3
#define TPB 256
#define G 1024                     // grid size

// Scratch (static __device__ — no allocation allowed)
__device__ float g_ce[NPRI];       // per-prior CE
__device__ float g_bg[NPRI];       // per-prior bg loss, -inf on positives
__device__ float g_cepart[G];      // per-block partial CE sum
__device__ float g_sl1part[G];     // per-block smooth-L1 partial
__device__ int   g_nppart[G];      // per-block positive-count partial
__device__ int   g_npos[BB];       // per-batch positive count (finisher-built)
__device__ float g_cesum[BB];      // per-batch masked CE (slow path)
__device__ int   g_ctr;            // k1 finisher counter (zero-init, reset each call)
__device__ int   g_ctr2;           // k2 finisher counter
__device__ int   g_fastdone;       // 1 => k1 already wrote out[]

__device__ __forceinline__ void cp16(uint32_t dst_smem, const void* src) {
    asm volatile("cp.async.cg.shared.global [%0], [%1], 16;" :: "r"(dst_smem), "l"(src));
}
__device__ __forceinline__ void cp_commit() {
    asm volatile("cp.async.commit_group;");
}
template <int N> __device__ __forceinline__ void cp_wait() {
    asm volatile("cp.async.wait_group %0;" :: "n"(N));
}

// ---------------------------------------------------------------------------
// k1: one fused kernel, G=1024 blocks, everything overlapped.
//  1) cp.async prologue: LOOKAHEAD conf tiles in flight
//  2) loc slice (~273 priors/block; slice bounds align with batch bounds)
//     — its LDG latency hides under the async fills
//  3) conf pipeline: wait<2> / barrier / compute / issue t+3 / commit
//  Last block: rebuild per-batch npos, allfast check, write out[] if fast.
// ---------------------------------------------------------------------------
__global__ void __launch_bounds__(TPB) k1(const float* __restrict__ conf,
                                          const float* __restrict__ pred,
                                          const float* __restrict__ gt,
                                          const int* __restrict__ labels,
                                          float* __restrict__ out) {
    __shared__ float4 stg[STAGES][STAGE_F4];   // 41984 B
    __shared__ float  sred[TPB];
    __shared__ float  sred2[TPB];
    __shared__ int    sint[TPB];
    __shared__ int    s_last;
    __shared__ int    s_fast;
    const int bx   = blockIdx.x;
    const int tid  = threadIdx.x;
    const int lane = tid & 31;
    const int wid  = tid >> 5;
    const unsigned FULL = 0xffffffffu;

    const int start = (int)(((long long)bx * NTILES) / G);
    const int end   = (int)(((long long)(bx + 1) * NTILES) / G);
    const float4* conf4 = reinterpret_cast<const float4*>(conf);
    const int4*   lab4  = reinterpret_cast<const int4*>(labels);

    auto issue = [&](int t, int s) {
        uint32_t sbase = (uint32_t)__cvta_generic_to_shared(&stg[s][0]);
        for (int i = tid; i < STAGE_F4; i += TPB) {
            const void* src = (i < TILE_F4)
                ? (const void*)(conf4 + (size_t)t * TILE_F4 + i)
                : (const void*)(lab4 + (size_t)t * LAB_F4 + (i - TILE_F4));
            cp16(sbase + (uint32_t)i * 16u, src);
        }
    };

    // ---- 1) prologue: LOOKAHEAD tiles in flight ----
    #pragma unroll
    for (int i = 0; i < LOOKAHEAD; i++) {
        if (start + i < end) issue(start + i, i);
        cp_commit();                       // always commit (group-count invariant)
    }

    // ---- 2) loc slice (overlaps the fills) ----
    {
        const int p0 = (int)(((long long)bx * NPRI) / G);
        const int p1 = (int)(((long long)(bx + 1) * NPRI) / G);
        int   np  = 0;
        float sl1 = 0.f;
        for (int p = p0 + tid; p < p1; p += TPB) {
            const int lab = labels[p];
            if (lab > 0) {
                np++;
                const float4 pv = *reinterpret_cast<const float4*>(pred + (size_t)p * 4);
                const float4 gv = *reinterpret_cast<const float4*>(gt   + (size_t)p * 4);
                float d, ad;
                d = pv.x - gv.x; ad = fabsf(d); sl1 += (ad < 1.f) ? 0.5f * d * d : ad - 0.5f;
                d = pv.y - gv.y; ad = fabsf(d); sl1 += (ad < 1.f) ? 0.5f * d * d : ad - 0.5f;
                d = pv.z - gv.z; ad = fabsf(d); sl1 += (ad < 1.f) ? 0.5f * d * d : ad - 0.5f;
                d = pv.w - gv.w; ad = fabsf(d); sl1 += (ad < 1.f) ? 0.5f * d * d : ad - 0.5f;
            }
        }
        sred[tid] = sl1;
        sint[tid] = np;
        __syncthreads();
        for (int st = TPB / 2; st > 0; st >>= 1) {
            if (tid < st) { sred[tid] += sred[tid + st]; sint[tid] += sint[tid + st]; }
            __syncthreads();
        }
        if (tid == 0) { g_sl1part[bx] = sred[0]; g_nppart[bx] = sint[0]; }
    }

    // ---- 3) conf pipeline ----
    float ce_acc = 0.f;
    const int row = (wid << 2) + (lane >> 3);  // 4 rows per warp
    const int sub = lane & 7;                  // 8 workers per row

    for (int t = start; t < end; t++) {
        const int s = (t - start) & (STAGES - 1);
        cp_wait<LOOKAHEAD - 1>();  // groups through tile t complete
        __syncthreads();           // visible block-wide; stage t-1 fully consumed

        const float* sp   = reinterpret_cast<const float*>(&stg[s][0]);
        const int*   slab = reinterpret_cast<const int*>(sp + TILE_FLOATS);
        const float* rp   = sp + row * CC;

        float a0 = 0.f, a1 = 0.f;
        #pragma unroll
        for (int k = 0; k < 10; k += 2) {
            a0 += __expf(rp[sub + 8 * k]);
            a1 += __expf(rp[sub + 8 * (k + 1)]);
        }
        float a = a0 + a1;
        const int lab = slab[row];
        if (sub == 0) a += __expf(rp[80]);
        a += __shfl_xor_sync(FULL, a, 1);
        a += __shfl_xor_sync(FULL, a, 2);
        a += __shfl_xor_sync(FULL, a, 4);
        if (sub == 0) {
            const float lse  = __logf(a);
            const float pick = rp[lab];
            const float x0   = rp[0];
            const float ce   = lse - pick;
            const int   rg   = t * TROWS + row;
            g_ce[rg] = ce;
            g_bg[rg] = (lab > 0) ? -INFINITY : (lse - x0);
            ce_acc += ce;
        }
        // issue tile t+LOOKAHEAD into the stage that held tile t-1
        const int tn = t + LOOKAHEAD;
        if (tn < end) issue(tn, (tn - start) & (STAGES - 1));
        cp_commit();               // always commit (keeps wait<2> aligned to tile t)
    }
    cp_wait<0>();

    // per-block CE partial (static tile assignment -> deterministic)
    sred[tid] = ce_acc;
    __syncthreads();
    for (int st = TPB / 2; st > 0; st >>= 1) {
        if (tid < st) sred[tid] += sred[tid + st];
        __syncthreads();
    }
    if (tid == 0) g_cepart[bx] = sred[0];

    // ---- finisher (last block of the grid) ----
    if (tid == 0) {
        __threadfence();
        s_last = (atomicAdd(&g_ctr, 1) == G - 1);
    }
    __syncthreads();
    if (!s_last) return;

    // rebuild per-batch npos: batch b == blocks [32b, 32b+32) exactly
    int slow = 0;
    if (tid < BB) {
        int np = 0;
        #pragma unroll
        for (int i = 0; i < 32; i++) np += g_nppart[tid * 32 + i];
        g_npos[tid] = np;
        slow = ((long long)np * 3 < (long long)PP);
    }
    const unsigned slowmask = __ballot_sync(FULL, (wid == 0) ? slow : 0);
    if (tid == 0) s_fast = (slowmask == 0u);
    __syncthreads();

    if (s_fast) {
        float cs = 0.f, sl = 0.f;
        for (int i = tid; i < G; i += TPB) { cs += g_cepart[i]; sl += g_sl1part[i]; }
        sred[tid]  = cs;
        sred2[tid] = sl;
        __syncthreads();
        for (int st = TPB / 2; st > 0; st >>= 1) {
            if (tid < st) { sred[tid] += sred[tid + st]; sred2[tid] += sred2[tid + st]; }
            __syncthreads();
        }
        if (tid < 32) {  // BB == 32
            int np = g_npos[tid];
            #pragma unroll
            for (int o = 16; o > 0; o >>= 1) np += __shfl_xor_sync(FULL, np, o);
            if (tid == 0) {
                const float inv = 1.f / (float)np;
                out[0] = sred2[0] * inv;
                out[1] = sred[0] * inv;
                g_fastdone = 1;
                g_ctr = 0;   // reset for next replay
            }
        }
    } else {
        if (tid == 0) { g_fastdone = 0; g_ctr = 0; }
    }
}

// ---------------------------------------------------------------------------
// k2: general path only (no-op when k1 already finalized).
// Per-batch: if num_neg >= P, sum that batch's CE directly; else exact
// hard-negative rank mining (stable-argsort tiebreak) over bg in smem.
// Last block combines and writes out[].
// ---------------------------------------------------------------------------
__global__ void __launch_bounds__(TPB) k2(float* __restrict__ out) {
    if (g_fastdone) return;

    __shared__ float sbg[PP];     // 34928 B
    __shared__ float sred[TPB];
    __shared__ int   s_last;
    const int b   = blockIdx.x;
    const int tid = threadIdx.x;
    const unsigned FULL = 0xffffffffu;
    const int np = g_npos[b];
    const long long num_neg = (long long)np * 3;
    const float* ce = g_ce + b * PP;

    float acc = 0.f;
    if (num_neg >= PP) {
        for (int p = tid; p < PP; p += TPB) acc += ce[p];
    } else {
        const float* bg = g_bg + b * PP;
        for (int p = tid; p < PP; p += TPB) sbg[p] = bg[p];
        __syncthreads();
        for (int p = tid; p < PP; p += TPB) {
            const float v = sbg[p];
            bool sel;
            if (v == -INFINITY) {
                sel = true;       // positive: always selected
            } else {
                int rank = 0;
                for (int j = 0; j < PP; j++) {
                    const float w = sbg[j];
                    rank += (w > v) || (w == v && j < p);
                }
                sel = (rank < num_neg);
            }
            if (sel) acc += ce[p];
        }
    }
    sred[tid] = acc;
    __syncthreads();
    for (int st = TPB / 2; st > 0; st >>= 1) {
        if (tid < st) sred[tid] += sred[tid + st];
        __syncthreads();
    }
    if (tid == 0) g_cesum[b] = sred[0];

    if (tid == 0) {
        __threadfence();
        s_last = (atomicAdd(&g_ctr2, 1) == BB - 1);
    }
    __syncthreads();
    if (!s_last) return;

    // total sl1 from the 1024 block partials (fixed order)
    float sl = 0.f;
    for (int i = tid; i < G; i += TPB) sl += g_sl1part[i];
    sred[tid] = sl;
    __syncthreads();
    for (int st = TPB / 2; st > 0; st >>= 1) {
        if (tid < st) sred[tid] += sred[tid + st];
        __syncthreads();
    }
    if (tid < 32) {  // BB == 32
        float cs = g_cesum[tid];
        int   tn = g_npos[tid];
        #pragma unroll
        for (int o = 16; o > 0; o >>= 1) {
            cs += __shfl_xor_sync(FULL, cs, o);
            tn += __shfl_xor_sync(FULL, tn, o);
        }
        if (tid == 0) {
            const float inv = 1.f / (float)tn;
            out[0] = sred[0] * inv;
            out[1] = cs * inv;
            g_ctr2 = 0;  // reset for next replay
        }
    }
}

// ---------------------------------------------------------------------------
extern "C" void kernel_launch(void* const* d_in, const int* in_sizes, int n_in,
                              void* d_out, int out_size) {
    const float* conf   = (const float*)d_in[0];   // (32, 8732, 81) f32
    const float* pred   = (const float*)d_in[1];   // (32, 8732, 4)  f32
    const int*   labels = (const int*)d_in[2];     // (32, 8732)     i32
    const float* gt     = (const float*)d_in[3];   // (32, 8732, 4)  f32
    float* out = (float*)d_out;                    // 2 floats

    k1<<<G, TPB>>>(conf, pred, gt, labels, out);
    k2<<<BB, TPB>>>(out);
}

// round 8
// speedup vs baseline: 1.6044x; 1.1533x over previous
#include <cuda_runtime.h>
#include <math.h>
#include <stdint.h>

// Problem shape (fixed by the reference setup_inputs)
#define BB 32
#define PP 8732
#define CC 81
#define NPRI (BB * PP)             // 279424 rows
#define TROWS 32                   // rows per tile
#define NTILES (NPRI / TROWS)      // 8732 (exact)
#define TILE_FLOATS (TROWS * CC)   // 2592
#define TILE_F4 (TILE_FLOATS / 4)  // 648
#define LAB_F4 (TROWS / 4)         // 8 (labels staged as int4)
#define STAGE_F4 (TILE_F4 + LAB_F4)// 656 float4 = 10496 B
#define STAGES 4                   // 41984 B of stages
#define LOOKAHEAD 3
#define TPB 256
#define G 736                      // 32*23: single wave at 5 blocks/SM on 148 SMs
#define BPB (G / BB)               // 23 blocks per batch (loc partials)

// Scratch (static __device__ — no allocation allowed)
__device__ float g_ce[NPRI];       // per-prior CE
__device__ float g_bg[NPRI];       // per-prior bg loss, -inf on positives
__device__ float g_cepart[G];      // per-block partial CE sum
__device__ float g_sl1part[G];     // per-block smooth-L1 partial
__device__ int   g_nppart[G];      // per-block positive-count partial
__device__ int   g_npos[BB];       // per-batch positive count (finisher-built)
__device__ int   g_ctr;            // finisher counter (zero-init, reset each call)

__device__ __forceinline__ void cp16(uint32_t dst_smem, const void* src) {
    asm volatile("cp.async.cg.shared.global [%0], [%1], 16;" :: "r"(dst_smem), "l"(src));
}
__device__ __forceinline__ void cp_commit() {
    asm volatile("cp.async.commit_group;");
}
template <int N> __device__ __forceinline__ void cp_wait() {
    asm volatile("cp.async.wait_group %0;" :: "n"(N));
}

// ---------------------------------------------------------------------------
// k1: the whole problem in one kernel, G=736 persistent blocks (single wave).
//  1) cp.async prologue: LOOKAHEAD conf tiles in flight
//  2) loc slice (~380 priors/block; slice bounds align with batch bounds)
//  3) conf pipeline: wait<2> / barrier / compute / issue t+3 / commit
//  4) last block finalizes: fast path (mask == all) sums block partials;
//     general path does exact per-batch hard-negative mining in-place.
// ---------------------------------------------------------------------------
__global__ void __launch_bounds__(TPB) k1(const float* __restrict__ conf,
                                          const float* __restrict__ pred,
                                          const float* __restrict__ gt,
                                          const int* __restrict__ labels,
                                          float* __restrict__ out) {
    __shared__ float4 stg[STAGES][STAGE_F4];   // 41984 B (reused by finisher)
    __shared__ float  sred[TPB];
    __shared__ int    sint[TPB];
    __shared__ int    s_last;
    __shared__ int    s_fast;
    __shared__ float  s_cs;
    const int bx   = blockIdx.x;
    const int tid  = threadIdx.x;
    const int lane = tid & 31;
    const int wid  = tid >> 5;
    const unsigned FULL = 0xffffffffu;

    const int start = (int)(((long long)bx * NTILES) / G);
    const int end   = (int)(((long long)(bx + 1) * NTILES) / G);
    const float4* conf4 = reinterpret_cast<const float4*>(conf);
    const int4*   lab4  = reinterpret_cast<const int4*>(labels);

    auto issue = [&](int t, int s) {
        uint32_t sbase = (uint32_t)__cvta_generic_to_shared(&stg[s][0]);
        for (int i = tid; i < STAGE_F4; i += TPB) {
            const void* src = (i < TILE_F4)
                ? (const void*)(conf4 + (size_t)t * TILE_F4 + i)
                : (const void*)(lab4 + (size_t)t * LAB_F4 + (i - TILE_F4));
            cp16(sbase + (uint32_t)i * 16u, src);
        }
    };

    // ---- 1) prologue: LOOKAHEAD tiles in flight ----
    #pragma unroll
    for (int i = 0; i < LOOKAHEAD; i++) {
        if (start + i < end) issue(start + i, i);
        cp_commit();                       // always commit (group-count invariant)
    }

    // ---- 2) loc slice (overlaps the fills) ----
    {
        const int p0 = (int)(((long long)bx * NPRI) / G);
        const int p1 = (int)(((long long)(bx + 1) * NPRI) / G);
        int   np  = 0;
        float sl1 = 0.f;
        for (int p = p0 + tid; p < p1; p += TPB) {
            const int lab = labels[p];
            if (lab > 0) {
                np++;
                const float4 pv = *reinterpret_cast<const float4*>(pred + (size_t)p * 4);
                const float4 gv = *reinterpret_cast<const float4*>(gt   + (size_t)p * 4);
                float d, ad;
                d = pv.x - gv.x; ad = fabsf(d); sl1 += (ad < 1.f) ? 0.5f * d * d : ad - 0.5f;
                d = pv.y - gv.y; ad = fabsf(d); sl1 += (ad < 1.f) ? 0.5f * d * d : ad - 0.5f;
                d = pv.z - gv.z; ad = fabsf(d); sl1 += (ad < 1.f) ? 0.5f * d * d : ad - 0.5f;
                d = pv.w - gv.w; ad = fabsf(d); sl1 += (ad < 1.f) ? 0.5f * d * d : ad - 0.5f;
            }
        }
        sred[tid] = sl1;
        sint[tid] = np;
        __syncthreads();
        for (int st = TPB / 2; st > 0; st >>= 1) {
            if (tid < st) { sred[tid] += sred[tid + st]; sint[tid] += sint[tid + st]; }
            __syncthreads();
        }
        if (tid == 0) { g_sl1part[bx] = sred[0]; g_nppart[bx] = sint[0]; }
    }

    // ---- 3) conf pipeline ----
    float ce_acc = 0.f;
    const int row = (wid << 2) + (lane >> 3);  // 4 rows per warp
    const int sub = lane & 7;                  // 8 workers per row

    for (int t = start; t < end; t++) {
        const int s = (t - start) & (STAGES - 1);
        cp_wait<LOOKAHEAD - 1>();  // groups through tile t complete
        __syncthreads();           // visible block-wide; stage t-1 fully consumed

        const float* sp   = reinterpret_cast<const float*>(&stg[s][0]);
        const int*   slab = reinterpret_cast<const int*>(sp + TILE_FLOATS);
        const float* rp   = sp + row * CC;

        float a0 = 0.f, a1 = 0.f;
        #pragma unroll
        for (int k = 0; k < 10; k += 2) {
            a0 += __expf(rp[sub + 8 * k]);
            a1 += __expf(rp[sub + 8 * (k + 1)]);
        }
        float a = a0 + a1;
        const int lab = slab[row];
        if (sub == 0) a += __expf(rp[80]);
        a += __shfl_xor_sync(FULL, a, 1);
        a += __shfl_xor_sync(FULL, a, 2);
        a += __shfl_xor_sync(FULL, a, 4);
        if (sub == 0) {
            const float lse  = __logf(a);
            const float pick = rp[lab];
            const float x0   = rp[0];
            const float ce   = lse - pick;
            const int   rg   = t * TROWS + row;
            g_ce[rg] = ce;
            g_bg[rg] = (lab > 0) ? -INFINITY : (lse - x0);
            ce_acc += ce;
        }
        // issue tile t+LOOKAHEAD into the stage that held tile t-1
        const int tn = t + LOOKAHEAD;
        if (tn < end) issue(tn, (tn - start) & (STAGES - 1));
        cp_commit();               // always commit (keeps wait<2> aligned to tile t)
    }
    cp_wait<0>();

    // per-block CE partial (static tile assignment -> deterministic)
    sred[tid] = ce_acc;
    __syncthreads();
    for (int st = TPB / 2; st > 0; st >>= 1) {
        if (tid < st) sred[tid] += sred[tid + st];
        __syncthreads();
    }
    if (tid == 0) g_cepart[bx] = sred[0];

    // ---- 4) finisher (last block of the grid) ----
    if (tid == 0) {
        __threadfence();
        s_last = (atomicAdd(&g_ctr, 1) == G - 1);
    }
    __syncthreads();
    if (!s_last) return;

    // rebuild per-batch npos: batch b == blocks [23b, 23b+23) exactly
    int slow = 0;
    if (tid < BB) {
        int np = 0;
        #pragma unroll
        for (int i = 0; i < BPB; i++) np += g_nppart[tid * BPB + i];
        g_npos[tid] = np;
        slow = ((long long)np * 3 < (long long)PP);
    }
    const unsigned slowmask = __ballot_sync(FULL, slow);  // warp 0's is meaningful
    if (tid == 0) s_fast = (slowmask == 0u);
    __syncthreads();

    if (s_fast) {
        // total CE = sum of all block partials (fixed order -> deterministic)
        float cs = 0.f;
        for (int i = tid; i < G; i += TPB) cs += g_cepart[i];
        sred[tid] = cs;
        __syncthreads();
        for (int st = TPB / 2; st > 0; st >>= 1) {
            if (tid < st) sred[tid] += sred[tid + st];
            __syncthreads();
        }
        if (tid == 0) s_cs = sred[0];
        __syncthreads();
    } else {
        // general path in-place (correctness fallback; O(P^2) mining per slow batch)
        float* sbg = reinterpret_cast<float*>(stg);   // reuse drained stages (>= PP floats)
        if (tid == 0) s_cs = 0.f;
        __syncthreads();
        for (int b = 0; b < BB; b++) {
            const int np = g_npos[b];
            const long long num_neg = (long long)np * 3;
            const float* ce = g_ce + b * PP;
            float acc = 0.f;
            if (num_neg >= PP) {
                for (int p = tid; p < PP; p += TPB) acc += ce[p];
            } else {
                const float* bg = g_bg + b * PP;
                for (int p = tid; p < PP; p += TPB) sbg[p] = bg[p];
                __syncthreads();
                for (int p = tid; p < PP; p += TPB) {
                    const float v = sbg[p];
                    bool sel;
                    if (v == -INFINITY) {
                        sel = true;  // positive: always selected
                    } else {
                        int rank = 0;
                        for (int j = 0; j < PP; j++) {
                            const float w = sbg[j];
                            rank += (w > v) || (w == v && j < p);  // stable-argsort tiebreak
                        }
                        sel = (rank < num_neg);
                    }
                    if (sel) acc += ce[p];
                }
                __syncthreads();   // before next batch reuses sbg
            }
            sred[tid] = acc;
            __syncthreads();
            for (int st = TPB / 2; st > 0; st >>= 1) {
                if (tid < st) sred[tid] += sred[tid + st];
                __syncthreads();
            }
            if (tid == 0) s_cs += sred[0];  // fixed batch order -> deterministic
            __syncthreads();
        }
    }

    // common tail: total smooth-L1 + total npos, write out[]
    float sl = 0.f;
    for (int i = tid; i < G; i += TPB) sl += g_sl1part[i];
    sred[tid] = sl;
    __syncthreads();
    for (int st = TPB / 2; st > 0; st >>= 1) {
        if (tid < st) sred[tid] += sred[tid + st];
        __syncthreads();
    }
    if (tid < 32) {  // BB == 32
        int np = g_npos[tid];
        #pragma unroll
        for (int o = 16; o > 0; o >>= 1) np += __shfl_xor_sync(FULL, np, o);
        if (tid == 0) {
            const float inv = 1.f / (float)np;
            out[0] = sred[0] * inv;
            out[1] = s_cs * inv;
            g_ctr = 0;   // reset for next replay
        }
    }
}

// ---------------------------------------------------------------------------
extern "C" void kernel_launch(void* const* d_in, const int* in_sizes, int n_in,
                              void* d_out, int out_size) {
    const float* conf   = (const float*)d_in[0];   // (32, 8732, 81) f32
    const float* pred   = (const float*)d_in[1];   // (32, 8732, 4)  f32
    const int*   labels = (const int*)d_in[2];     // (32, 8732)     i32
    const float* gt     = (const float*)d_in[3];   // (32, 8732, 4)  f32
    float* out = (float*)d_out;                    // 2 floats

    k1<<<G, TPB>>>(conf, pred, gt, labels, out);
}